// round 1
// baseline (speedup 1.0000x reference)
#include <cuda_runtime.h>

#define N_USERS 60000
#define M_ITEMS 40000
#define NNODES  100000
#define D       64
#define NLAYERS 3
#define BSZ     1024
#define NEG     0.2f

// Scratch: current features x and SpMM result lie (25.6 MB each).
__device__ __align__(16) float g_x[NNODES * D];
__device__ __align__(16) float g_lie[NNODES * D];

// ---------------------------------------------------------------------------
// Build x0 = concat(embed_user, embed_item)
// ---------------------------------------------------------------------------
__global__ void init_x_kernel(const float* __restrict__ eu, const float* __restrict__ ei) {
    int t = blockIdx.x * blockDim.x + threadIdx.x;
    const int total = NNODES * D / 4;
    if (t >= total) return;
    const int uElems = N_USERS * D / 4;
    float4 v = (t < uElems) ? ((const float4*)eu)[t] : ((const float4*)ei)[t - uElems];
    ((float4*)g_x)[t] = v;
}

__global__ void zero_lie_kernel() {
    int t = blockIdx.x * blockDim.x + threadIdx.x;
    if (t < NNODES * D / 4) ((float4*)g_lie)[t] = make_float4(0.f, 0.f, 0.f, 0.f);
}

// ---------------------------------------------------------------------------
// SpMM: lie[row] += val * x[col].  16 threads per edge, float4 per thread,
// vector reduction (red.global.add.v4.f32) -> 256B contiguous atomics/edge.
// ---------------------------------------------------------------------------
__global__ void spmm_kernel(const int* __restrict__ er, const int* __restrict__ ec,
                            const float* __restrict__ ev, int nnz) {
    int t = blockIdx.x * blockDim.x + threadIdx.x;
    int e = t >> 4;
    if (e >= nnz) return;
    int lane = t & 15;
    int r = __ldg(er + e);
    int c = __ldg(ec + e);
    float v = __ldg(ev + e);
    float4 xv = *((const float4*)(g_x + (size_t)c * D) + lane);
    float* dst = g_lie + (size_t)r * D + (size_t)lane * 4;
    asm volatile("red.global.add.v4.f32 [%0], {%1,%2,%3,%4};"
                 :: "l"(dst), "f"(v * xv.x), "f"(v * xv.y), "f"(v * xv.z), "f"(v * xv.w)
                 : "memory");
}

// ---------------------------------------------------------------------------
// Transform: x = leaky_relu( lie@W1 + (x*lie)@W2 + b1 + b2 ), in place.
// Block: 64 nodes x 64 outputs, 256 threads, 4x4 register tile each.
// W1/W2 resident in SMEM; A tiles staged transposed [k][m] with stride 68
// (16B-aligned rows, broadcast-friendly float4 reads).
// ---------------------------------------------------------------------------
#define A_STRIDE 68
#define SMEM_FLOATS (4096 * 2 + A_STRIDE * 64 * 2 + 64)

__global__ void transform_kernel(const float* __restrict__ W1, const float* __restrict__ W2,
                                 const float* __restrict__ b1, const float* __restrict__ b2) {
    extern __shared__ float sh[];
    float* Ws1 = sh;                       // [64][64]
    float* Ws2 = Ws1 + 4096;               // [64][64]
    float* As1 = Ws2 + 4096;               // [64][A_STRIDE]  (lie, transposed)
    float* As2 = As1 + A_STRIDE * 64;      // [64][A_STRIDE]  (x*lie, transposed)
    float* bs  = As2 + A_STRIDE * 64;      // [64] = b1 + b2

    int tid = threadIdx.x;

    for (int i = tid; i < 1024; i += 256) {
        ((float4*)Ws1)[i] = ((const float4*)W1)[i];
        ((float4*)Ws2)[i] = ((const float4*)W2)[i];
    }
    if (tid < 64) bs[tid] = b1[tid] + b2[tid];

    int node0 = blockIdx.x * 64;

    // Stage A transposed: 64 nodes x 64 k.
    for (int i = tid; i < 1024; i += 256) {
        int m  = i >> 4;            // node within tile
        int k4 = (i & 15) << 2;     // k base
        int node = node0 + m;
        float4 l4 = make_float4(0.f, 0.f, 0.f, 0.f);
        float4 xv = l4;
        if (node < NNODES) {
            l4 = *(const float4*)(g_lie + (size_t)node * D + k4);
            xv = *(const float4*)(g_x   + (size_t)node * D + k4);
        }
        As1[(k4 + 0) * A_STRIDE + m] = l4.x;
        As1[(k4 + 1) * A_STRIDE + m] = l4.y;
        As1[(k4 + 2) * A_STRIDE + m] = l4.z;
        As1[(k4 + 3) * A_STRIDE + m] = l4.w;
        As2[(k4 + 0) * A_STRIDE + m] = l4.x * xv.x;
        As2[(k4 + 1) * A_STRIDE + m] = l4.y * xv.y;
        As2[(k4 + 2) * A_STRIDE + m] = l4.z * xv.z;
        As2[(k4 + 3) * A_STRIDE + m] = l4.w * xv.w;
    }
    __syncthreads();

    int ng = tid & 15;   // output group: columns ng*4..+3
    int mg = tid >> 4;   // node group:   nodes   mg*4..+3

    float acc[4][4];
    #pragma unroll
    for (int m = 0; m < 4; m++)
        #pragma unroll
        for (int n = 0; n < 4; n++) acc[m][n] = 0.f;

    #pragma unroll 8
    for (int k = 0; k < 64; k++) {
        float4 a1 = *(const float4*)&As1[k * A_STRIDE + mg * 4];
        float4 a2 = *(const float4*)&As2[k * A_STRIDE + mg * 4];
        float4 w1 = *(const float4*)&Ws1[k * 64 + ng * 4];
        float4 w2 = *(const float4*)&Ws2[k * 64 + ng * 4];
        float a1v[4] = {a1.x, a1.y, a1.z, a1.w};
        float a2v[4] = {a2.x, a2.y, a2.z, a2.w};
        float w1v[4] = {w1.x, w1.y, w1.z, w1.w};
        float w2v[4] = {w2.x, w2.y, w2.z, w2.w};
        #pragma unroll
        for (int m = 0; m < 4; m++)
            #pragma unroll
            for (int n = 0; n < 4; n++)
                acc[m][n] += a1v[m] * w1v[n] + a2v[m] * w2v[n];
    }

    #pragma unroll
    for (int m = 0; m < 4; m++) {
        int node = node0 + mg * 4 + m;
        if (node < NNODES) {
            float4 o;
            float vx = acc[m][0] + bs[ng * 4 + 0];
            float vy = acc[m][1] + bs[ng * 4 + 1];
            float vz = acc[m][2] + bs[ng * 4 + 2];
            float vw = acc[m][3] + bs[ng * 4 + 3];
            o.x = (vx > 0.f) ? vx : NEG * vx;
            o.y = (vy > 0.f) ? vy : NEG * vy;
            o.z = (vz > 0.f) ? vz : NEG * vz;
            o.w = (vw > 0.f) ? vw : NEG * vw;
            *(float4*)(g_x + (size_t)node * D + ng * 4) = o;
        }
    }
}

// ---------------------------------------------------------------------------
// Gather the 3*B selected rows' current-layer slice into the output.
// out layout: [3][B][4*D]; layer slice at column layer*D.
// ---------------------------------------------------------------------------
__global__ void gather_kernel(const int* __restrict__ users, const int* __restrict__ obs,
                              const int* __restrict__ unobs, float* __restrict__ out,
                              int layer) {
    int t = blockIdx.x * blockDim.x + threadIdx.x;
    if (t >= 3 * BSZ * (D / 4)) return;
    int j4 = t & 15;              // float4 index within D
    int b  = (t >> 4) & (BSZ - 1);
    int g  = t >> 14;             // 0: users, 1: observed, 2: unobserved
    int node = (g == 0) ? users[b] : ((g == 1) ? N_USERS + obs[b] : N_USERS + unobs[b]);
    float4 v = *(const float4*)(g_x + (size_t)node * D + j4 * 4);
    *(float4*)(out + (size_t)(g * BSZ + b) * (4 * D) + layer * D + j4 * 4) = v;
}

// ---------------------------------------------------------------------------
extern "C" void kernel_launch(void* const* d_in, const int* in_sizes, int n_in,
                              void* d_out, int out_size) {
    const int*   er = (const int*)d_in[0];
    const int*   ec = (const int*)d_in[1];
    const float* ev = (const float*)d_in[2];
    const float* eu = (const float*)d_in[3];
    const float* ei = (const float*)d_in[4];
    const float* W1 = (const float*)d_in[5];
    const float* W2 = (const float*)d_in[6];
    const float* b1 = (const float*)d_in[7];
    const float* b2 = (const float*)d_in[8];
    const int*   su = (const int*)d_in[9];
    const int*   oi = (const int*)d_in[10];
    const int*   ui = (const int*)d_in[11];
    float* out = (float*)d_out;
    int nnz = in_sizes[0];

    const int smemBytes = SMEM_FLOATS * 4;
    cudaFuncSetAttribute(transform_kernel, cudaFuncAttributeMaxDynamicSharedMemorySize, smemBytes);

    const int cpBlocks = (NNODES * D / 4 + 255) / 256;
    const int gBlocks  = (3 * BSZ * (D / 4) + 255) / 256;

    init_x_kernel<<<cpBlocks, 256>>>(eu, ei);
    gather_kernel<<<gBlocks, 256>>>(su, oi, ui, out, 0);

    for (int i = 0; i < NLAYERS; i++) {
        zero_lie_kernel<<<cpBlocks, 256>>>();
        long long spThreads = (long long)nnz * 16;
        int spBlocks = (int)((spThreads + 255) / 256);
        spmm_kernel<<<spBlocks, 256>>>(er, ec, ev, nnz);
        transform_kernel<<<(NNODES + 63) / 64, 256, smemBytes>>>(
            W1 + (size_t)i * D * D, W2 + (size_t)i * D * D,
            b1 + (size_t)i * D,     b2 + (size_t)i * D);
        gather_kernel<<<gBlocks, 256>>>(su, oi, ui, out, i + 1);
    }
}

// round 2
// speedup vs baseline: 1.3881x; 1.3881x over previous
#include <cuda_runtime.h>

#define N_USERS 60000
#define M_ITEMS 40000
#define NNODES  100000
#define D       64
#define NLAYERS 3
#define BSZ     1024
#define NEG     0.2f
#define NNZ_MAX 3200000
#define EDGE_MAX 6400000   // nnz + 31*NNODES padding worst case
#define SCAN_NB 99         // ceil((NNODES+1)/1024)

// Scratch
__device__ __align__(16) float g_x[NNODES * D];
__device__ __align__(16) float g_lie[NNODES * D];
__device__ __align__(16) int2  g_edges[EDGE_MAX];   // (col, val bits)
__device__ int g_cnt[NNODES];
__device__ int g_cur[NNODES];
__device__ int g_rowstart[NNODES + 1];
__device__ int g_bsum[SCAN_NB];
__device__ int g_boff[SCAN_NB];

// ---------------------------------------------------------------------------
// x0 = concat(embed_user, embed_item)
// ---------------------------------------------------------------------------
__global__ void init_x_kernel(const float* __restrict__ eu, const float* __restrict__ ei) {
    int t = blockIdx.x * blockDim.x + threadIdx.x;
    const int total = NNODES * D / 4;
    if (t >= total) return;
    const int uElems = N_USERS * D / 4;
    float4 v = (t < uElems) ? ((const float4*)eu)[t] : ((const float4*)ei)[t - uElems];
    ((float4*)g_x)[t] = v;
}

// ---------------------------------------------------------------------------
// CSR build (per launch, deterministic up to fp-accumulation order)
// ---------------------------------------------------------------------------
__global__ void zero_cnt_kernel() {
    int t = blockIdx.x * blockDim.x + threadIdx.x;
    if (t < NNODES) { g_cnt[t] = 0; g_cur[t] = 0; }
}

__global__ void zero_edges_kernel() {
    int t = blockIdx.x * blockDim.x + threadIdx.x;
    if (t < EDGE_MAX / 2) ((int4*)g_edges)[t] = make_int4(0, 0, 0, 0);
}

__global__ void hist_kernel(const int* __restrict__ er, int nnz) {
    int e = blockIdx.x * blockDim.x + threadIdx.x;
    if (e < nnz) atomicAdd(&g_cnt[er[e]], 1);
}

// Exclusive scan of padded counts. padded = ceil(cnt/32)*32.
__global__ void scan_block_kernel() {
    __shared__ int sd[1024];
    int i = blockIdx.x * 1024 + threadIdx.x;
    int v = 0;
    if (i < NNODES) v = (g_cnt[i] + 31) & ~31;
    sd[threadIdx.x] = v;
    __syncthreads();
    #pragma unroll
    for (int off = 1; off < 1024; off <<= 1) {
        int t = (threadIdx.x >= off) ? sd[threadIdx.x - off] : 0;
        __syncthreads();
        sd[threadIdx.x] += t;
        __syncthreads();
    }
    if (i <= NNODES) g_rowstart[i] = sd[threadIdx.x] - v;   // exclusive
    if (threadIdx.x == 1023) g_bsum[blockIdx.x] = sd[1023];
}

__global__ void scan_top_kernel() {
    __shared__ int sd[128];
    int v = (threadIdx.x < SCAN_NB) ? g_bsum[threadIdx.x] : 0;
    sd[threadIdx.x] = v;
    __syncthreads();
    #pragma unroll
    for (int off = 1; off < 128; off <<= 1) {
        int t = (threadIdx.x >= off) ? sd[threadIdx.x - off] : 0;
        __syncthreads();
        sd[threadIdx.x] += t;
        __syncthreads();
    }
    if (threadIdx.x < SCAN_NB) g_boff[threadIdx.x] = sd[threadIdx.x] - v;  // exclusive
}

__global__ void scan_add_kernel() {
    int i = blockIdx.x * blockDim.x + threadIdx.x;
    if (i <= NNODES) g_rowstart[i] += g_boff[i >> 10];
}

__global__ void scatter_kernel(const int* __restrict__ er, const int* __restrict__ ec,
                               const float* __restrict__ ev, int nnz) {
    int e = blockIdx.x * blockDim.x + threadIdx.x;
    if (e >= nnz) return;
    int r = er[e];
    int pos = g_rowstart[r] + atomicAdd(&g_cur[r], 1);
    g_edges[pos] = make_int2(ec[e], __float_as_int(ev[e]));
}

// ---------------------------------------------------------------------------
// SpMM over padded CSR: one warp per row, lane owns float2 of the 64 features.
// Chunks of 32 edges: coalesced int2 edge load, shfl-broadcast (col,val),
// 32 independent 8B gathers -> high MLP, single store per row. No atomics.
// ---------------------------------------------------------------------------
__global__ void spmm_csr_kernel() {
    int row = (blockIdx.x * blockDim.x + threadIdx.x) >> 5;
    if (row >= NNODES) return;
    int lane = threadIdx.x & 31;
    int start = g_rowstart[row];
    int end   = g_rowstart[row + 1];
    float2 acc = make_float2(0.f, 0.f);
    const int2* ep = g_edges + start;
    int nchunk = (end - start) >> 5;
    for (int c = 0; c < nchunk; c++) {
        int2 ed = ep[(c << 5) + lane];
        #pragma unroll
        for (int k = 0; k < 32; k++) {
            int   col = __shfl_sync(0xffffffffu, ed.x, k);
            float val = __int_as_float(__shfl_sync(0xffffffffu, ed.y, k));
            float2 xv = *(const float2*)(g_x + (size_t)col * D + lane * 2);
            acc.x += val * xv.x;
            acc.y += val * xv.y;
        }
    }
    *(float2*)(g_lie + (size_t)row * D + lane * 2) = acc;
}

// ---------------------------------------------------------------------------
// Transform: x = leaky_relu( lie@W1 + (x*lie)@W2 + b1 + b2 ), in place.
// ---------------------------------------------------------------------------
#define A_STRIDE 68
#define SMEM_FLOATS (4096 * 2 + A_STRIDE * 64 * 2 + 64)

__global__ void transform_kernel(const float* __restrict__ W1, const float* __restrict__ W2,
                                 const float* __restrict__ b1, const float* __restrict__ b2) {
    extern __shared__ float sh[];
    float* Ws1 = sh;
    float* Ws2 = Ws1 + 4096;
    float* As1 = Ws2 + 4096;
    float* As2 = As1 + A_STRIDE * 64;
    float* bs  = As2 + A_STRIDE * 64;

    int tid = threadIdx.x;
    for (int i = tid; i < 1024; i += 256) {
        ((float4*)Ws1)[i] = ((const float4*)W1)[i];
        ((float4*)Ws2)[i] = ((const float4*)W2)[i];
    }
    if (tid < 64) bs[tid] = b1[tid] + b2[tid];

    int node0 = blockIdx.x * 64;
    for (int i = tid; i < 1024; i += 256) {
        int m  = i >> 4;
        int k4 = (i & 15) << 2;
        int node = node0 + m;
        float4 l4 = make_float4(0.f, 0.f, 0.f, 0.f);
        float4 xv = l4;
        if (node < NNODES) {
            l4 = *(const float4*)(g_lie + (size_t)node * D + k4);
            xv = *(const float4*)(g_x   + (size_t)node * D + k4);
        }
        As1[(k4 + 0) * A_STRIDE + m] = l4.x;
        As1[(k4 + 1) * A_STRIDE + m] = l4.y;
        As1[(k4 + 2) * A_STRIDE + m] = l4.z;
        As1[(k4 + 3) * A_STRIDE + m] = l4.w;
        As2[(k4 + 0) * A_STRIDE + m] = l4.x * xv.x;
        As2[(k4 + 1) * A_STRIDE + m] = l4.y * xv.y;
        As2[(k4 + 2) * A_STRIDE + m] = l4.z * xv.z;
        As2[(k4 + 3) * A_STRIDE + m] = l4.w * xv.w;
    }
    __syncthreads();

    int ng = tid & 15;
    int mg = tid >> 4;

    float acc[4][4];
    #pragma unroll
    for (int m = 0; m < 4; m++)
        #pragma unroll
        for (int n = 0; n < 4; n++) acc[m][n] = 0.f;

    #pragma unroll 8
    for (int k = 0; k < 64; k++) {
        float4 a1 = *(const float4*)&As1[k * A_STRIDE + mg * 4];
        float4 a2 = *(const float4*)&As2[k * A_STRIDE + mg * 4];
        float4 w1 = *(const float4*)&Ws1[k * 64 + ng * 4];
        float4 w2 = *(const float4*)&Ws2[k * 64 + ng * 4];
        float a1v[4] = {a1.x, a1.y, a1.z, a1.w};
        float a2v[4] = {a2.x, a2.y, a2.z, a2.w};
        float w1v[4] = {w1.x, w1.y, w1.z, w1.w};
        float w2v[4] = {w2.x, w2.y, w2.z, w2.w};
        #pragma unroll
        for (int m = 0; m < 4; m++)
            #pragma unroll
            for (int n = 0; n < 4; n++)
                acc[m][n] += a1v[m] * w1v[n] + a2v[m] * w2v[n];
    }

    #pragma unroll
    for (int m = 0; m < 4; m++) {
        int node = node0 + mg * 4 + m;
        if (node < NNODES) {
            float4 o;
            float vx = acc[m][0] + bs[ng * 4 + 0];
            float vy = acc[m][1] + bs[ng * 4 + 1];
            float vz = acc[m][2] + bs[ng * 4 + 2];
            float vw = acc[m][3] + bs[ng * 4 + 3];
            o.x = (vx > 0.f) ? vx : NEG * vx;
            o.y = (vy > 0.f) ? vy : NEG * vy;
            o.z = (vz > 0.f) ? vz : NEG * vz;
            o.w = (vw > 0.f) ? vw : NEG * vw;
            *(float4*)(g_x + (size_t)node * D + ng * 4) = o;
        }
    }
}

// ---------------------------------------------------------------------------
// Gather selected rows' layer slice into d_out: [3][B][4*D]
// ---------------------------------------------------------------------------
__global__ void gather_kernel(const int* __restrict__ users, const int* __restrict__ obs,
                              const int* __restrict__ unobs, float* __restrict__ out,
                              int layer) {
    int t = blockIdx.x * blockDim.x + threadIdx.x;
    if (t >= 3 * BSZ * (D / 4)) return;
    int j4 = t & 15;
    int b  = (t >> 4) & (BSZ - 1);
    int g  = t >> 14;
    int node = (g == 0) ? users[b] : ((g == 1) ? N_USERS + obs[b] : N_USERS + unobs[b]);
    float4 v = *(const float4*)(g_x + (size_t)node * D + j4 * 4);
    *(float4*)(out + (size_t)(g * BSZ + b) * (4 * D) + layer * D + j4 * 4) = v;
}

// ---------------------------------------------------------------------------
extern "C" void kernel_launch(void* const* d_in, const int* in_sizes, int n_in,
                              void* d_out, int out_size) {
    const int*   er = (const int*)d_in[0];
    const int*   ec = (const int*)d_in[1];
    const float* ev = (const float*)d_in[2];
    const float* eu = (const float*)d_in[3];
    const float* ei = (const float*)d_in[4];
    const float* W1 = (const float*)d_in[5];
    const float* W2 = (const float*)d_in[6];
    const float* b1 = (const float*)d_in[7];
    const float* b2 = (const float*)d_in[8];
    const int*   su = (const int*)d_in[9];
    const int*   oi = (const int*)d_in[10];
    const int*   ui = (const int*)d_in[11];
    float* out = (float*)d_out;
    int nnz = in_sizes[0];

    const int smemBytes = SMEM_FLOATS * 4;
    cudaFuncSetAttribute(transform_kernel, cudaFuncAttributeMaxDynamicSharedMemorySize, smemBytes);

    const int cpBlocks = (NNODES * D / 4 + 255) / 256;
    const int gBlocks  = (3 * BSZ * (D / 4) + 255) / 256;
    const int eBlocks  = (nnz + 255) / 256;

    // CSR build
    zero_cnt_kernel<<<(NNODES + 255) / 256, 256>>>();
    zero_edges_kernel<<<(EDGE_MAX / 2 + 255) / 256, 256>>>();
    hist_kernel<<<eBlocks, 256>>>(er, nnz);
    scan_block_kernel<<<SCAN_NB, 1024>>>();
    scan_top_kernel<<<1, 128>>>();
    scan_add_kernel<<<(NNODES + 256) / 256, 256>>>();
    scatter_kernel<<<eBlocks, 256>>>(er, ec, ev, nnz);

    init_x_kernel<<<cpBlocks, 256>>>(eu, ei);
    gather_kernel<<<gBlocks, 256>>>(su, oi, ui, out, 0);

    for (int i = 0; i < NLAYERS; i++) {
        spmm_csr_kernel<<<(NNODES * 32 + 255) / 256, 256>>>();
        transform_kernel<<<(NNODES + 63) / 64, 256, smemBytes>>>(
            W1 + (size_t)i * D * D, W2 + (size_t)i * D * D,
            b1 + (size_t)i * D,     b2 + (size_t)i * D);
        gather_kernel<<<gBlocks, 256>>>(su, oi, ui, out, i + 1);
    }
}

// round 3
// speedup vs baseline: 1.4707x; 1.0595x over previous
#include <cuda_runtime.h>
#include <cuda_fp16.h>

#define N_USERS 60000
#define M_ITEMS 40000
#define NNODES  100000
#define D       64
#define NLAYERS 3
#define BSZ     1024
#define NEG     0.2f
#define EDGE_MAX 6400000
#define SCAN_NB 99

// Scratch
__device__ __align__(16) float   g_x[NNODES * D];
__device__ __align__(16) __half2 g_xh[NNODES * (D / 2)];   // fp16 mirror for SpMM gather
__device__ __align__(16) float   g_lie[NNODES * D];
__device__ __align__(16) int2    g_edges[EDGE_MAX];
__device__ int g_cnt[NNODES];
__device__ int g_cur[NNODES];
__device__ int g_rowstart[NNODES + 1];
__device__ int g_bsum[SCAN_NB];
__device__ int g_boff[SCAN_NB];

// ---------------------------------------------------------------------------
// x0 = concat(embed_user, embed_item); also fill fp16 mirror
// ---------------------------------------------------------------------------
__global__ void init_x_kernel(const float* __restrict__ eu, const float* __restrict__ ei) {
    int t = blockIdx.x * blockDim.x + threadIdx.x;
    const int total = NNODES * D / 4;
    if (t >= total) return;
    const int uElems = N_USERS * D / 4;
    float4 v = (t < uElems) ? ((const float4*)eu)[t] : ((const float4*)ei)[t - uElems];
    ((float4*)g_x)[t] = v;
    g_xh[t * 2 + 0] = __floats2half2_rn(v.x, v.y);
    g_xh[t * 2 + 1] = __floats2half2_rn(v.z, v.w);
}

// ---------------------------------------------------------------------------
// CSR build
// ---------------------------------------------------------------------------
__global__ void zero_cnt_kernel() {
    int t = blockIdx.x * blockDim.x + threadIdx.x;
    if (t < NNODES) { g_cnt[t] = 0; g_cur[t] = 0; }
}

__global__ void hist_kernel(const int* __restrict__ er, int nnz) {
    int e = blockIdx.x * blockDim.x + threadIdx.x;
    if (e < nnz) atomicAdd(&g_cnt[er[e]], 1);
}

__global__ void scan_block_kernel() {
    __shared__ int sd[1024];
    int i = blockIdx.x * 1024 + threadIdx.x;
    int v = 0;
    if (i < NNODES) v = (g_cnt[i] + 31) & ~31;
    sd[threadIdx.x] = v;
    __syncthreads();
    #pragma unroll
    for (int off = 1; off < 1024; off <<= 1) {
        int t = (threadIdx.x >= off) ? sd[threadIdx.x - off] : 0;
        __syncthreads();
        sd[threadIdx.x] += t;
        __syncthreads();
    }
    if (i <= NNODES) g_rowstart[i] = sd[threadIdx.x] - v;
    if (threadIdx.x == 1023) g_bsum[blockIdx.x] = sd[1023];
}

__global__ void scan_top_kernel() {
    __shared__ int sd[128];
    int v = (threadIdx.x < SCAN_NB) ? g_bsum[threadIdx.x] : 0;
    sd[threadIdx.x] = v;
    __syncthreads();
    #pragma unroll
    for (int off = 1; off < 128; off <<= 1) {
        int t = (threadIdx.x >= off) ? sd[threadIdx.x - off] : 0;
        __syncthreads();
        sd[threadIdx.x] += t;
        __syncthreads();
    }
    if (threadIdx.x < SCAN_NB) g_boff[threadIdx.x] = sd[threadIdx.x] - v;
}

__global__ void scan_add_kernel() {
    int i = blockIdx.x * blockDim.x + threadIdx.x;
    if (i <= NNODES) g_rowstart[i] += g_boff[i >> 10];
}

__global__ void scatter_kernel(const int* __restrict__ er, const int* __restrict__ ec,
                               const float* __restrict__ ev, int nnz) {
    int e = blockIdx.x * blockDim.x + threadIdx.x;
    if (e >= nnz) return;
    int r = er[e];
    int pos = g_rowstart[r] + atomicAdd(&g_cur[r], 1);
    g_edges[pos] = make_int2(ec[e], __float_as_int(ev[e]));
}

// Fill only each row's padding tail (col=0, val=0). One warp per row.
__global__ void pad_kernel() {
    int row = blockIdx.x * 8 + (threadIdx.x >> 5);
    if (row >= NNODES) return;
    int lane = threadIdx.x & 31;
    int cnt = g_cnt[row];
    int pad = ((cnt + 31) & ~31) - cnt;
    if (lane < pad) g_edges[g_rowstart[row] + cnt + lane] = make_int2(0, 0);
}

// ---------------------------------------------------------------------------
// SpMM over padded CSR, fp16 gather payload, fp32 accumulate.
// One warp per row; lane owns 2 features (one half2 = 4B -> 128B/row gather).
// Edges staged via SMEM (broadcast LDS instead of 64 SHFLs per chunk).
// ---------------------------------------------------------------------------
__global__ void spmm_csr_kernel() {
    __shared__ int2 sed[8][32];
    int warp = threadIdx.x >> 5;
    int lane = threadIdx.x & 31;
    int row = blockIdx.x * 8 + warp;
    if (row >= NNODES) return;
    int start = g_rowstart[row];
    int end   = g_rowstart[row + 1];
    float2 acc = make_float2(0.f, 0.f);
    const int2* ep = g_edges + start;
    int nchunk = (end - start) >> 5;
    for (int c = 0; c < nchunk; c++) {
        sed[warp][lane] = ep[(c << 5) + lane];
        __syncwarp();
        #pragma unroll
        for (int k = 0; k < 32; k++) {
            int2 e = sed[warp][k];
            float2 xf = __half22float2(g_xh[(size_t)e.x * (D / 2) + lane]);
            float v = __int_as_float(e.y);
            acc.x += v * xf.x;
            acc.y += v * xf.y;
        }
        __syncwarp();
    }
    *(float2*)(g_lie + (size_t)row * D + lane * 2) = acc;
}

// ---------------------------------------------------------------------------
// Transform: x = leaky_relu( lie@W1 + (x*lie)@W2 + b1 + b2 ), in place.
// Also refreshes the fp16 mirror.
// ---------------------------------------------------------------------------
#define A_STRIDE 68
#define SMEM_FLOATS (4096 * 2 + A_STRIDE * 64 * 2 + 64)

__global__ void transform_kernel(const float* __restrict__ W1, const float* __restrict__ W2,
                                 const float* __restrict__ b1, const float* __restrict__ b2) {
    extern __shared__ float sh[];
    float* Ws1 = sh;
    float* Ws2 = Ws1 + 4096;
    float* As1 = Ws2 + 4096;
    float* As2 = As1 + A_STRIDE * 64;
    float* bs  = As2 + A_STRIDE * 64;

    int tid = threadIdx.x;
    for (int i = tid; i < 1024; i += 256) {
        ((float4*)Ws1)[i] = ((const float4*)W1)[i];
        ((float4*)Ws2)[i] = ((const float4*)W2)[i];
    }
    if (tid < 64) bs[tid] = b1[tid] + b2[tid];

    int node0 = blockIdx.x * 64;
    for (int i = tid; i < 1024; i += 256) {
        int m  = i >> 4;
        int k4 = (i & 15) << 2;
        int node = node0 + m;
        float4 l4 = make_float4(0.f, 0.f, 0.f, 0.f);
        float4 xv = l4;
        if (node < NNODES) {
            l4 = *(const float4*)(g_lie + (size_t)node * D + k4);
            xv = *(const float4*)(g_x   + (size_t)node * D + k4);
        }
        As1[(k4 + 0) * A_STRIDE + m] = l4.x;
        As1[(k4 + 1) * A_STRIDE + m] = l4.y;
        As1[(k4 + 2) * A_STRIDE + m] = l4.z;
        As1[(k4 + 3) * A_STRIDE + m] = l4.w;
        As2[(k4 + 0) * A_STRIDE + m] = l4.x * xv.x;
        As2[(k4 + 1) * A_STRIDE + m] = l4.y * xv.y;
        As2[(k4 + 2) * A_STRIDE + m] = l4.z * xv.z;
        As2[(k4 + 3) * A_STRIDE + m] = l4.w * xv.w;
    }
    __syncthreads();

    int ng = tid & 15;
    int mg = tid >> 4;

    float acc[4][4];
    #pragma unroll
    for (int m = 0; m < 4; m++)
        #pragma unroll
        for (int n = 0; n < 4; n++) acc[m][n] = 0.f;

    #pragma unroll 8
    for (int k = 0; k < 64; k++) {
        float4 a1 = *(const float4*)&As1[k * A_STRIDE + mg * 4];
        float4 a2 = *(const float4*)&As2[k * A_STRIDE + mg * 4];
        float4 w1 = *(const float4*)&Ws1[k * 64 + ng * 4];
        float4 w2 = *(const float4*)&Ws2[k * 64 + ng * 4];
        float a1v[4] = {a1.x, a1.y, a1.z, a1.w};
        float a2v[4] = {a2.x, a2.y, a2.z, a2.w};
        float w1v[4] = {w1.x, w1.y, w1.z, w1.w};
        float w2v[4] = {w2.x, w2.y, w2.z, w2.w};
        #pragma unroll
        for (int m = 0; m < 4; m++)
            #pragma unroll
            for (int n = 0; n < 4; n++)
                acc[m][n] += a1v[m] * w1v[n] + a2v[m] * w2v[n];
    }

    #pragma unroll
    for (int m = 0; m < 4; m++) {
        int node = node0 + mg * 4 + m;
        if (node < NNODES) {
            float4 o;
            float vx = acc[m][0] + bs[ng * 4 + 0];
            float vy = acc[m][1] + bs[ng * 4 + 1];
            float vz = acc[m][2] + bs[ng * 4 + 2];
            float vw = acc[m][3] + bs[ng * 4 + 3];
            o.x = (vx > 0.f) ? vx : NEG * vx;
            o.y = (vy > 0.f) ? vy : NEG * vy;
            o.z = (vz > 0.f) ? vz : NEG * vz;
            o.w = (vw > 0.f) ? vw : NEG * vw;
            *(float4*)(g_x + (size_t)node * D + ng * 4) = o;
            g_xh[(size_t)node * (D / 2) + ng * 2 + 0] = __floats2half2_rn(o.x, o.y);
            g_xh[(size_t)node * (D / 2) + ng * 2 + 1] = __floats2half2_rn(o.z, o.w);
        }
    }
}

// ---------------------------------------------------------------------------
// Gather selected rows' layer slice into d_out: [3][B][4*D]
// ---------------------------------------------------------------------------
__global__ void gather_kernel(const int* __restrict__ users, const int* __restrict__ obs,
                              const int* __restrict__ unobs, float* __restrict__ out,
                              int layer) {
    int t = blockIdx.x * blockDim.x + threadIdx.x;
    if (t >= 3 * BSZ * (D / 4)) return;
    int j4 = t & 15;
    int b  = (t >> 4) & (BSZ - 1);
    int g  = t >> 14;
    int node = (g == 0) ? users[b] : ((g == 1) ? N_USERS + obs[b] : N_USERS + unobs[b]);
    float4 v = *(const float4*)(g_x + (size_t)node * D + j4 * 4);
    *(float4*)(out + (size_t)(g * BSZ + b) * (4 * D) + layer * D + j4 * 4) = v;
}

// ---------------------------------------------------------------------------
extern "C" void kernel_launch(void* const* d_in, const int* in_sizes, int n_in,
                              void* d_out, int out_size) {
    const int*   er = (const int*)d_in[0];
    const int*   ec = (const int*)d_in[1];
    const float* ev = (const float*)d_in[2];
    const float* eu = (const float*)d_in[3];
    const float* ei = (const float*)d_in[4];
    const float* W1 = (const float*)d_in[5];
    const float* W2 = (const float*)d_in[6];
    const float* b1 = (const float*)d_in[7];
    const float* b2 = (const float*)d_in[8];
    const int*   su = (const int*)d_in[9];
    const int*   oi = (const int*)d_in[10];
    const int*   ui = (const int*)d_in[11];
    float* out = (float*)d_out;
    int nnz = in_sizes[0];

    const int smemBytes = SMEM_FLOATS * 4;
    cudaFuncSetAttribute(transform_kernel, cudaFuncAttributeMaxDynamicSharedMemorySize, smemBytes);

    const int cpBlocks = (NNODES * D / 4 + 255) / 256;
    const int gBlocks  = (3 * BSZ * (D / 4) + 255) / 256;
    const int eBlocks  = (nnz + 255) / 256;
    const int rwBlocks = (NNODES + 7) / 8;   // warp-per-row kernels

    // CSR build
    zero_cnt_kernel<<<(NNODES + 255) / 256, 256>>>();
    hist_kernel<<<eBlocks, 256>>>(er, nnz);
    scan_block_kernel<<<SCAN_NB, 1024>>>();
    scan_top_kernel<<<1, 128>>>();
    scan_add_kernel<<<(NNODES + 256) / 256, 256>>>();
    scatter_kernel<<<eBlocks, 256>>>(er, ec, ev, nnz);
    pad_kernel<<<rwBlocks, 256>>>();

    init_x_kernel<<<cpBlocks, 256>>>(eu, ei);
    gather_kernel<<<gBlocks, 256>>>(su, oi, ui, out, 0);

    for (int i = 0; i < NLAYERS; i++) {
        spmm_csr_kernel<<<rwBlocks, 256>>>();
        transform_kernel<<<(NNODES + 63) / 64, 256, smemBytes>>>(
            W1 + (size_t)i * D * D, W2 + (size_t)i * D * D,
            b1 + (size_t)i * D,     b2 + (size_t)i * D);
        gather_kernel<<<gBlocks, 256>>>(su, oi, ui, out, i + 1);
    }
}

// round 4
// speedup vs baseline: 1.7606x; 1.1971x over previous
#include <cuda_runtime.h>
#include <cuda_fp16.h>
#include <cstdint>

#define N_USERS 60000
#define M_ITEMS 40000
#define NNODES  100000
#define D       64
#define NLAYERS 3
#define BSZ     1024
#define NEG     0.2f
#define EDGE_MAX 6400000
#define SCAN_NB 99
#define SA      72            // half-element stride for SMEM tiles (conflict-free)

// Scratch
__device__ __align__(16) float   g_x[NNODES * D];            // fp32 features
__device__ __align__(16) __half2 g_xh[NNODES * (D / 2)];     // fp16 mirror (SpMM gather)
__device__ __align__(16) __half2 g_lieh[NNODES * (D / 2)];   // fp16 lie
__device__ __align__(16) __half2 g_prodh[NNODES * (D / 2)];  // fp16 x*lie
__device__ __align__(16) int2    g_edges[EDGE_MAX];
__device__ int g_cnt[NNODES];
__device__ int g_cur[NNODES];
__device__ int g_rowstart[NNODES + 1];
__device__ int g_bsum[SCAN_NB];
__device__ int g_boff[SCAN_NB];

// ---------------------------------------------------------------------------
// x0 = concat(embed_user, embed_item); fill fp16 mirror
// ---------------------------------------------------------------------------
__global__ void init_x_kernel(const float* __restrict__ eu, const float* __restrict__ ei) {
    int t = blockIdx.x * blockDim.x + threadIdx.x;
    const int total = NNODES * D / 4;
    if (t >= total) return;
    const int uElems = N_USERS * D / 4;
    float4 v = (t < uElems) ? ((const float4*)eu)[t] : ((const float4*)ei)[t - uElems];
    ((float4*)g_x)[t] = v;
    g_xh[t * 2 + 0] = __floats2half2_rn(v.x, v.y);
    g_xh[t * 2 + 1] = __floats2half2_rn(v.z, v.w);
}

// ---------------------------------------------------------------------------
// CSR build (unchanged from round 3)
// ---------------------------------------------------------------------------
__global__ void zero_cnt_kernel() {
    int t = blockIdx.x * blockDim.x + threadIdx.x;
    if (t < NNODES) { g_cnt[t] = 0; g_cur[t] = 0; }
}

__global__ void hist_kernel(const int* __restrict__ er, int nnz) {
    int e = blockIdx.x * blockDim.x + threadIdx.x;
    if (e < nnz) atomicAdd(&g_cnt[er[e]], 1);
}

__global__ void scan_block_kernel() {
    __shared__ int sd[1024];
    int i = blockIdx.x * 1024 + threadIdx.x;
    int v = 0;
    if (i < NNODES) v = (g_cnt[i] + 31) & ~31;
    sd[threadIdx.x] = v;
    __syncthreads();
    #pragma unroll
    for (int off = 1; off < 1024; off <<= 1) {
        int t = (threadIdx.x >= off) ? sd[threadIdx.x - off] : 0;
        __syncthreads();
        sd[threadIdx.x] += t;
        __syncthreads();
    }
    if (i <= NNODES) g_rowstart[i] = sd[threadIdx.x] - v;
    if (threadIdx.x == 1023) g_bsum[blockIdx.x] = sd[1023];
}

__global__ void scan_top_kernel() {
    __shared__ int sd[128];
    int v = (threadIdx.x < SCAN_NB) ? g_bsum[threadIdx.x] : 0;
    sd[threadIdx.x] = v;
    __syncthreads();
    #pragma unroll
    for (int off = 1; off < 128; off <<= 1) {
        int t = (threadIdx.x >= off) ? sd[threadIdx.x - off] : 0;
        __syncthreads();
        sd[threadIdx.x] += t;
        __syncthreads();
    }
    if (threadIdx.x < SCAN_NB) g_boff[threadIdx.x] = sd[threadIdx.x] - v;
}

__global__ void scan_add_kernel() {
    int i = blockIdx.x * blockDim.x + threadIdx.x;
    if (i <= NNODES) g_rowstart[i] += g_boff[i >> 10];
}

__global__ void scatter_kernel(const int* __restrict__ er, const int* __restrict__ ec,
                               const float* __restrict__ ev, int nnz) {
    int e = blockIdx.x * blockDim.x + threadIdx.x;
    if (e >= nnz) return;
    int r = er[e];
    int pos = g_rowstart[r] + atomicAdd(&g_cur[r], 1);
    g_edges[pos] = make_int2(ec[e], __float_as_int(ev[e]));
}

__global__ void pad_kernel() {
    int row = blockIdx.x * 8 + (threadIdx.x >> 5);
    if (row >= NNODES) return;
    int lane = threadIdx.x & 31;
    int cnt = g_cnt[row];
    int pad = ((cnt + 31) & ~31) - cnt;
    if (lane < pad) g_edges[g_rowstart[row] + cnt + lane] = make_int2(0, 0);
}

// ---------------------------------------------------------------------------
// SpMM over padded CSR: fp16 gather, fp32 accumulate.
// Epilogue writes fp16 lie and fp16 (x*lie) for the MMA transform.
// ---------------------------------------------------------------------------
__global__ void spmm_csr_kernel() {
    __shared__ int2 sed[8][32];
    int warp = threadIdx.x >> 5;
    int lane = threadIdx.x & 31;
    int row = blockIdx.x * 8 + warp;
    if (row >= NNODES) return;
    int start = g_rowstart[row];
    int end   = g_rowstart[row + 1];
    float2 acc = make_float2(0.f, 0.f);
    const int2* ep = g_edges + start;
    int nchunk = (end - start) >> 5;
    for (int c = 0; c < nchunk; c++) {
        sed[warp][lane] = ep[(c << 5) + lane];
        __syncwarp();
        #pragma unroll
        for (int k = 0; k < 32; k++) {
            int2 e = sed[warp][k];
            float2 xf = __half22float2(g_xh[(size_t)e.x * (D / 2) + lane]);
            float v = __int_as_float(e.y);
            acc.x += v * xf.x;
            acc.y += v * xf.y;
        }
        __syncwarp();
    }
    float2 xv = *(const float2*)(g_x + (size_t)row * D + lane * 2);
    g_lieh[(size_t)row * (D / 2) + lane]  = __floats2half2_rn(acc.x, acc.y);
    g_prodh[(size_t)row * (D / 2) + lane] = __floats2half2_rn(acc.x * xv.x, acc.y * xv.y);
}

// ---------------------------------------------------------------------------
// Transform via tensor cores:
// x = leaky_relu( lieh@W1h + prodh@W2h + b1 + b2 ), fp32 accumulate.
// Tile: 128 nodes x 64 outputs, 8 warps, warp = 16 rows. mma.m16n8k16.
// SMEM operands padded to stride 72 halves => conflict-free LDS.32.
// ---------------------------------------------------------------------------
#define TR_SMEM_BYTES (2 * 128 * SA * 2 + 2 * 64 * SA * 2 + 64 * 4)

__device__ __forceinline__ void mma_16816(float* c, uint32_t a0, uint32_t a1,
                                          uint32_t a2, uint32_t a3,
                                          uint32_t b0, uint32_t b1) {
    asm volatile(
        "mma.sync.aligned.m16n8k16.row.col.f32.f16.f16.f32 "
        "{%0,%1,%2,%3}, {%4,%5,%6,%7}, {%8,%9}, {%0,%1,%2,%3};"
        : "+f"(c[0]), "+f"(c[1]), "+f"(c[2]), "+f"(c[3])
        : "r"(a0), "r"(a1), "r"(a2), "r"(a3), "r"(b0), "r"(b1));
}

__global__ __launch_bounds__(256) void transform_mma_kernel(
        const float* __restrict__ W1, const float* __restrict__ W2,
        const float* __restrict__ b1, const float* __restrict__ b2) {
    extern __shared__ __half sh[];
    __half* As1 = sh;                    // [128][SA]
    __half* As2 = As1 + 128 * SA;        // [128][SA]
    __half* Wt1 = As2 + 128 * SA;        // [64][SA]  W1 transposed: [n][k]
    __half* Wt2 = Wt1 + 64 * SA;         // [64][SA]
    float*  bs  = (float*)(Wt2 + 64 * SA);

    int tid = threadIdx.x;
    int node0 = blockIdx.x * 128;

    // Stage A (lie, x*lie) as half2, zero-fill OOB rows.
    __half2* As1_2 = (__half2*)As1;      // row stride SA/2 = 36
    __half2* As2_2 = (__half2*)As2;
    for (int i = tid; i < 128 * 32; i += 256) {
        int m = i >> 5, j = i & 31;
        int node = node0 + m;
        __half2 l = __float2half2_rn(0.f), p = l;
        if (node < NNODES) {
            l = g_lieh[(size_t)node * 32 + j];
            p = g_prodh[(size_t)node * 32 + j];
        }
        As1_2[m * (SA / 2) + j] = l;
        As2_2[m * (SA / 2) + j] = p;
    }
    // Stage W transposed: Wt[n][k] = W[k][n]
    for (int i = tid; i < 4096; i += 256) {
        int k = i >> 6, n = i & 63;
        Wt1[n * SA + k] = __float2half_rn(W1[i]);
        Wt2[n * SA + k] = __float2half_rn(W2[i]);
    }
    if (tid < 64) bs[tid] = b1[tid] + b2[tid];
    __syncthreads();

    int wid = tid >> 5, lane = tid & 31;
    int r = lane >> 2, c = lane & 3;
    int mrow = wid * 16 + r;

    float acc[8][4];
    #pragma unroll
    for (int nt = 0; nt < 8; nt++)
        #pragma unroll
        for (int j = 0; j < 4; j++) acc[nt][j] = 0.f;

    #pragma unroll
    for (int kt = 0; kt < 4; kt++) {
        int ko = kt * 16 + c * 2;
        uint32_t a0 = *(const uint32_t*)(As1 + mrow * SA + ko);
        uint32_t a1 = *(const uint32_t*)(As1 + (mrow + 8) * SA + ko);
        uint32_t a2 = *(const uint32_t*)(As1 + mrow * SA + ko + 8);
        uint32_t a3 = *(const uint32_t*)(As1 + (mrow + 8) * SA + ko + 8);
        uint32_t e0 = *(const uint32_t*)(As2 + mrow * SA + ko);
        uint32_t e1 = *(const uint32_t*)(As2 + (mrow + 8) * SA + ko);
        uint32_t e2 = *(const uint32_t*)(As2 + mrow * SA + ko + 8);
        uint32_t e3 = *(const uint32_t*)(As2 + (mrow + 8) * SA + ko + 8);
        #pragma unroll
        for (int nt = 0; nt < 8; nt++) {
            uint32_t b0 = *(const uint32_t*)(Wt1 + (nt * 8 + r) * SA + ko);
            uint32_t b1v = *(const uint32_t*)(Wt1 + (nt * 8 + r) * SA + ko + 8);
            mma_16816(acc[nt], a0, a1, a2, a3, b0, b1v);
            uint32_t d0 = *(const uint32_t*)(Wt2 + (nt * 8 + r) * SA + ko);
            uint32_t d1 = *(const uint32_t*)(Wt2 + (nt * 8 + r) * SA + ko + 8);
            mma_16816(acc[nt], e0, e1, e2, e3, d0, d1);
        }
    }

    // Epilogue: bias + leaky relu, write fp32 x and fp16 mirror.
    int m0 = node0 + mrow;
    int m1 = m0 + 8;
    #pragma unroll
    for (int nt = 0; nt < 8; nt++) {
        int n0 = nt * 8 + c * 2;
        float bx = bs[n0], by = bs[n0 + 1];
        if (m0 < NNODES) {
            float vx = acc[nt][0] + bx, vy = acc[nt][1] + by;
            vx = (vx > 0.f) ? vx : NEG * vx;
            vy = (vy > 0.f) ? vy : NEG * vy;
            *(float2*)(g_x + (size_t)m0 * D + n0) = make_float2(vx, vy);
            g_xh[(size_t)m0 * 32 + n0 / 2] = __floats2half2_rn(vx, vy);
        }
        if (m1 < NNODES) {
            float vx = acc[nt][2] + bx, vy = acc[nt][3] + by;
            vx = (vx > 0.f) ? vx : NEG * vx;
            vy = (vy > 0.f) ? vy : NEG * vy;
            *(float2*)(g_x + (size_t)m1 * D + n0) = make_float2(vx, vy);
            g_xh[(size_t)m1 * 32 + n0 / 2] = __floats2half2_rn(vx, vy);
        }
    }
}

// ---------------------------------------------------------------------------
// Gather selected rows' layer slice into d_out: [3][B][4*D]
// ---------------------------------------------------------------------------
__global__ void gather_kernel(const int* __restrict__ users, const int* __restrict__ obs,
                              const int* __restrict__ unobs, float* __restrict__ out,
                              int layer) {
    int t = blockIdx.x * blockDim.x + threadIdx.x;
    if (t >= 3 * BSZ * (D / 4)) return;
    int j4 = t & 15;
    int b  = (t >> 4) & (BSZ - 1);
    int g  = t >> 14;
    int node = (g == 0) ? users[b] : ((g == 1) ? N_USERS + obs[b] : N_USERS + unobs[b]);
    float4 v = *(const float4*)(g_x + (size_t)node * D + j4 * 4);
    *(float4*)(out + (size_t)(g * BSZ + b) * (4 * D) + layer * D + j4 * 4) = v;
}

// ---------------------------------------------------------------------------
extern "C" void kernel_launch(void* const* d_in, const int* in_sizes, int n_in,
                              void* d_out, int out_size) {
    const int*   er = (const int*)d_in[0];
    const int*   ec = (const int*)d_in[1];
    const float* ev = (const float*)d_in[2];
    const float* eu = (const float*)d_in[3];
    const float* ei = (const float*)d_in[4];
    const float* W1 = (const float*)d_in[5];
    const float* W2 = (const float*)d_in[6];
    const float* b1 = (const float*)d_in[7];
    const float* b2 = (const float*)d_in[8];
    const int*   su = (const int*)d_in[9];
    const int*   oi = (const int*)d_in[10];
    const int*   ui = (const int*)d_in[11];
    float* out = (float*)d_out;
    int nnz = in_sizes[0];

    cudaFuncSetAttribute(transform_mma_kernel,
                         cudaFuncAttributeMaxDynamicSharedMemorySize, TR_SMEM_BYTES);

    const int cpBlocks = (NNODES * D / 4 + 255) / 256;
    const int gBlocks  = (3 * BSZ * (D / 4) + 255) / 256;
    const int eBlocks  = (nnz + 255) / 256;
    const int rwBlocks = (NNODES + 7) / 8;
    const int trBlocks = (NNODES + 127) / 128;

    // CSR build
    zero_cnt_kernel<<<(NNODES + 255) / 256, 256>>>();
    hist_kernel<<<eBlocks, 256>>>(er, nnz);
    scan_block_kernel<<<SCAN_NB, 1024>>>();
    scan_top_kernel<<<1, 128>>>();
    scan_add_kernel<<<(NNODES + 256) / 256, 256>>>();
    scatter_kernel<<<eBlocks, 256>>>(er, ec, ev, nnz);
    pad_kernel<<<rwBlocks, 256>>>();

    init_x_kernel<<<cpBlocks, 256>>>(eu, ei);
    gather_kernel<<<gBlocks, 256>>>(su, oi, ui, out, 0);

    for (int i = 0; i < NLAYERS; i++) {
        spmm_csr_kernel<<<rwBlocks, 256>>>();
        transform_mma_kernel<<<trBlocks, 256, TR_SMEM_BYTES>>>(
            W1 + (size_t)i * D * D, W2 + (size_t)i * D * D,
            b1 + (size_t)i * D,     b2 + (size_t)i * D);
        gather_kernel<<<gBlocks, 256>>>(su, oi, ui, out, i + 1);
    }
}